// round 15
// baseline (speedup 1.0000x reference)
#include <cuda_runtime.h>
#include <cuda_bf16.h>
#include <cstdint>
#include <math.h>

#define NMAX 16384
__device__ __align__(256) float g_stackedT[(size_t)NMAX * 2048];
__device__ __align__(256) uint32_t g_Ah[(size_t)NMAX * 1024];   // [tile][r][kp]
__device__ __align__(256) uint32_t g_Al[(size_t)NMAX * 1024];
__device__ __align__(256) uint32_t g_wBh[144 * 1024];           // [n][kp]
__device__ __align__(256) uint32_t g_wBl[144 * 1024];
__device__ __align__(256) uint32_t g_wSh[16 * 256 * 64];        // [v][n][kp]
__device__ __align__(256) uint32_t g_wSl[16 * 256 * 64];

static __device__ __forceinline__ float eluf(float t) {
    return t > 0.f ? t : __expf(t) - 1.f;
}
static __device__ __forceinline__ float sigm(float t) {
    return __fdividef(1.f, 1.f + __expf(-t));
}
static __device__ __forceinline__ uint32_t pk_bf2(float lo, float hi) {
    uint32_t r;
    asm("cvt.rn.bf16x2.f32 %0, %1, %2;" : "=r"(r) : "f"(hi), "f"(lo));
    return r;
}
static __device__ __forceinline__ void bsplit2(float x0, float x1,
                                               uint32_t& hp, uint32_t& lp) {
    float h0 = __bfloat162float(__float2bfloat16(x0));
    float h1 = __bfloat162float(__float2bfloat16(x1));
    hp = pk_bf2(h0, h1);
    lp = pk_bf2(x0 - h0, x1 - h1);
}
static __device__ __forceinline__ void mma16(float* c, const uint32_t* a,
                                             uint32_t b0, uint32_t b1) {
    asm volatile(
        "mma.sync.aligned.m16n8k16.row.col.f32.bf16.bf16.f32 "
        "{%0,%1,%2,%3}, {%4,%5,%6,%7}, {%8,%9}, {%0,%1,%2,%3};"
        : "+f"(c[0]), "+f"(c[1]), "+f"(c[2]), "+f"(c[3])
        : "r"(a[0]), "r"(a[1]), "r"(a[2]), "r"(a[3]), "r"(b0), "r"(b1));
}
static __device__ __forceinline__ void ldsm4(uint32_t* r, uint32_t a) {
    asm volatile("ldmatrix.sync.aligned.m8n8.x4.shared.b16 {%0,%1,%2,%3}, [%4];"
        : "=r"(r[0]), "=r"(r[1]), "=r"(r[2]), "=r"(r[3]) : "r"(a));
}
static __device__ __forceinline__ void ldsm2(uint32_t* r, uint32_t a) {
    asm volatile("ldmatrix.sync.aligned.m8n8.x2.shared.b16 {%0,%1}, [%2];"
        : "=r"(r[0]), "=r"(r[1]) : "r"(a));
}
static __device__ __forceinline__ uint32_t smaddr(const void* p) {
    return (uint32_t)__cvta_generic_to_shared(p);
}

// ---------------------------------------------------------------------------
// prep_weights: one-time bf16 split of all GEMM weights into hi/lo planes.
// ---------------------------------------------------------------------------
__global__ void __launch_bounds__(256) prep_weights(
    const float* __restrict__ sW1, const float* __restrict__ sWs,
    const float* __restrict__ W2, const float* __restrict__ Wg)
{
    const int T1 = 144 * 1024;
    const int T2 = 16 * 256 * 64;
    for (int idx = blockIdx.x * 256 + threadIdx.x; idx < T1 + T2;
         idx += gridDim.x * 256) {
        uint32_t hp, lp;
        if (idx < T1) {
            int n = idx >> 10, kp = idx & 1023;
            const float* src = (n < 128)
                ? sW1 + (size_t)n * 2048 + kp * 2
                : sWs + (size_t)(n - 128) * 2048 + kp * 2;
            float2 a = *(const float2*)src;
            bsplit2(a.x, a.y, hp, lp);
            g_wBh[idx] = hp;
            g_wBl[idx] = lp;
        } else {
            int j = idx - T1;
            int v = j >> 14, rem = j & 16383;
            int n = rem >> 6, kp = rem & 63;
            const float* src = (n < 128)
                ? W2 + ((size_t)v * 128 + n) * 128 + kp * 2
                : Wg + ((size_t)v * 128 + (n - 128)) * 128 + kp * 2;
            float2 a = *(const float2*)src;
            bsplit2(a.x, a.y, hp, lp);
            g_wSh[j] = hp;
            g_wSl[j] = lp;
        }
    }
}

// ---------------------------------------------------------------------------
// Stage 1 (bf16 mma, ldmatrix A+B, plane staging): grid (N/128, 16), 512 thr.
// ---------------------------------------------------------------------------
#define SM1_FLOATS 36224
__global__ void __launch_bounds__(512, 1) vsn_stage1(
    const float* __restrict__ x,
    const float* __restrict__ W1, const float* __restrict__ b1,
    const float* __restrict__ b2, const float* __restrict__ bg,
    const float* __restrict__ Ws, const float* __restrict__ bs,
    const float* __restrict__ gamma, const float* __restrict__ beta)
{
    extern __shared__ float sm[];
    uint32_t* A_hi = (uint32_t*)sm;            // [128][20]
    uint32_t* A_lo = (uint32_t*)(sm + 2560);
    uint32_t* B_hi = (uint32_t*)(sm + 5120);   // [256][20]
    uint32_t* B_lo = (uint32_t*)(sm + 10240);  // ends 15360
    float* arr1 = sm;               // [128][133] (post-GEMM overlay)
    float* arr2 = sm + 17024;       // [128][133]
    float* par  = sm + 34048;
    float* sx   = sm + 34816;
    float* pmean = sm + 34944;
    float* prstd = sm + 35072;
    float* part_s = sm + 35200;
    float* part_q = sm + 35712;

    const int tid = threadIdx.x, wid = tid >> 5, lane = tid & 31;
    const int mp = wid & 3, nq = wid >> 2;
    const int v = blockIdx.y;
    const int r0 = blockIdx.x * 128;
    const int ar = lane >> 2, ac = lane & 3;

    if (tid < 128) {
        sx[tid] = x[(size_t)(r0 + tid) * 16 + v];
        int o = tid;
        par[o]       = b2[v * 128 + o];
        par[128 + o] = bg[v * 128 + o];
        par[256 + o] = Ws[v * 128 + o];
        par[384 + o] = bs[v * 128 + o];
        par[512 + o] = gamma[v * 128 + o];
        par[640 + o] = beta[v * 128 + o];
    }

    float cfr[2][8][4];
    #pragma unroll
    for (int mi = 0; mi < 2; mi++)
        #pragma unroll
        for (int nt = 0; nt < 8; nt++)
            #pragma unroll
            for (int q = 0; q < 4; q++) cfr[mi][nt][q] = 0.f;

    const uint32_t sbAh = smaddr(A_hi), sbAl = smaddr(A_lo);
    const uint32_t sbBh = smaddr(B_hi), sbBl = smaddr(B_lo);
    const int lr = lane & 7, lm8 = (lane >> 3) & 1, lt = lane >> 4;
    // A ldmatrix row offsets: [m0k0, m8k0, m0k8, m8k8]
    const uint32_t offA = (uint32_t)((mp * 32 + lr + lm8 * 8) * 20 + lt * 4);
    uint32_t offB[4];
    #pragma unroll
    for (int p = 0; p < 4; p++)
        offB[p] = (uint32_t)((nq * 64 + p * 16 + lt * 8 + lr) * 20 + lm8 * 4);

    for (int kc = 0; kc < 4; kc++) {
        __syncthreads();
        const float* W1v = W1 + v * 128 + kc * 32;
        const float* b1v = b1 + v * 128 + kc * 32;
        for (int idx = tid; idx < 2048; idx += 512) {
            int r = idx & 127, kp = idx >> 7;
            int d = kp * 2;
            float xr = sx[r];
            float h0 = eluf(fmaf(xr, W1v[d], b1v[d]));
            float h1 = eluf(fmaf(xr, W1v[d + 1], b1v[d + 1]));
            uint32_t hp, lp;
            bsplit2(h0, h1, hp, lp);
            A_hi[r * 20 + kp] = hp;
            A_lo[r * 20 + kp] = lp;
        }
        // B chunk: uint4 plane copies
        for (int idx = tid; idx < 2048; idx += 512) {
            int plane = idx >> 10, j = idx & 1023;
            int n = j >> 2, kq = j & 3;
            const uint32_t* src = (plane ? g_wSl : g_wSh)
                + (((size_t)v * 256 + n) << 6) + kc * 16 + kq * 4;
            uint32_t* dst = (plane ? B_lo : B_hi) + n * 20 + kq * 4;
            *(uint4*)dst = *(const uint4*)src;
        }
        __syncthreads();

        #pragma unroll
        for (int ks = 0; ks < 2; ks++) {
            const int k0p = ks * 8;
            uint32_t aH[2][4], aL[2][4];
            ldsm4(aH[0], sbAh + (offA + k0p) * 4);
            ldsm4(aH[1], sbAh + (offA + 320 + k0p) * 4);
            ldsm4(aL[0], sbAl + (offA + k0p) * 4);
            ldsm4(aL[1], sbAl + (offA + 320 + k0p) * 4);
            uint32_t bH[16];
            #pragma unroll
            for (int p = 0; p < 4; p++)
                ldsm4(bH + p * 4, sbBh + (offB[p] + k0p) * 4);
            #pragma unroll
            for (int nt = 0; nt < 8; nt++) {
                int base = (nt >> 1) * 4 + (nt & 1) * 2;
                uint32_t b0 = bH[base], b1 = bH[base + 1];
                mma16(cfr[0][nt], aH[0], b0, b1);
                mma16(cfr[1][nt], aH[1], b0, b1);
                mma16(cfr[0][nt], aL[0], b0, b1);
                mma16(cfr[1][nt], aL[1], b0, b1);
            }
            uint32_t bL[16];
            #pragma unroll
            for (int p = 0; p < 4; p++)
                ldsm4(bL + p * 4, sbBl + (offB[p] + k0p) * 4);
            #pragma unroll
            for (int nt = 0; nt < 8; nt++) {
                int base = (nt >> 1) * 4 + (nt & 1) * 2;
                uint32_t b0 = bL[base], b1 = bL[base + 1];
                mma16(cfr[0][nt], aH[0], b0, b1);
                mma16(cfr[1][nt], aH[1], b0, b1);
            }
        }
    }
    __syncthreads();

    {
        const int ac2 = ac * 2;
        #pragma unroll
        for (int mi = 0; mi < 2; mi++) {
            #pragma unroll
            for (int half = 0; half < 2; half++) {
                int r = mp * 32 + mi * 16 + ar + half * 8;
                #pragma unroll
                for (int nt = 0; nt < 8; nt++) {
                    int n = (nq & 1) * 64 + nt * 8 + ac2;
                    float v0 = cfr[mi][nt][half * 2];
                    float v1 = cfr[mi][nt][half * 2 + 1];
                    if (nq < 2) {
                        arr1[r * 133 + n]     = v0 + par[n];
                        arr1[r * 133 + n + 1] = v1 + par[n + 1];
                    } else {
                        arr2[r * 133 + n]     = sigm(v0 + par[128 + n]);
                        arr2[r * 133 + n + 1] = sigm(v1 + par[128 + n + 1]);
                    }
                }
            }
        }
    }
    __syncthreads();

    {
        int r = tid & 127, hf = tid >> 7;
        float xr = sx[r];
        float s = 0.f, s2 = 0.f;
        int o0 = hf * 32;
        for (int o = o0; o < o0 + 32; o++) {
            float h2 = arr1[r * 133 + o];
            float g  = arr2[r * 133 + o];
            float sk = fmaf(xr, par[256 + o], par[384 + o]);
            float yv = g * h2 + (1.f - g) * sk;
            arr1[r * 133 + o] = yv;
            s += yv;
            s2 = fmaf(yv, yv, s2);
        }
        part_s[hf * 128 + r] = s;
        part_q[hf * 128 + r] = s2;
    }
    __syncthreads();
    if (tid < 128) {
        float s  = part_s[tid] + part_s[128 + tid] + part_s[256 + tid] + part_s[384 + tid];
        float s2 = part_q[tid] + part_q[128 + tid] + part_q[256 + tid] + part_q[384 + tid];
        float m = s * 0.0078125f;
        pmean[tid] = m;
        prstd[tid] = rsqrtf(fmaf(-m, m, s2 * 0.0078125f) + 1e-5f);
    }
    __syncthreads();

    // pass A: normalize in place + stackedT write (r-fast, coalesced)
    for (int idx = tid; idx < 16384; idx += 512) {
        int o = idx >> 7, r = idx & 127;
        float val = fmaf((arr1[r * 133 + o] - pmean[r]) * prstd[r],
                         par[512 + o], par[640 + o]);
        arr1[r * 133 + o] = val;
        size_t tile = (size_t)blockIdx.x * 2 + (r >> 6);
        g_stackedT[(tile * 2048 + v * 128 + o) * 64 + (r & 63)] = val;
    }
    __syncthreads();
    // pass B: split + plane write (kp-fast, coalesced)
    for (int idx = tid; idx < 8192; idx += 512) {
        int kpl = idx & 63, r = idx >> 6;
        float v0 = arr1[r * 133 + kpl * 2];
        float v1 = arr1[r * 133 + kpl * 2 + 1];
        uint32_t hp, lp;
        bsplit2(v0, v1, hp, lp);
        size_t tile = (size_t)blockIdx.x * 2 + (r >> 6);
        size_t base = ((tile * 64 + (r & 63)) << 10) + v * 64 + kpl;
        g_Ah[base] = hp;
        g_Al[base] = lp;
    }
}

// ---------------------------------------------------------------------------
// Stage 2 v5: bf16 mma, ldmatrix A+B, plane staging. grid N/64, 256 thr,
// 2 CTAs/SM. 8 warps = mp(4 m16) x nh(2: 9 n8-tiles). A/B smem stride 36.
// ---------------------------------------------------------------------------
#define S2_FLOATS 22400
__global__ void __launch_bounds__(256, 2) vsn_stage2(
    const float* __restrict__ sb1,
    const float* __restrict__ sW2, const float* __restrict__ sb2,
    const float* __restrict__ sWg, const float* __restrict__ sbg,
    const float* __restrict__ sbs,
    const float* __restrict__ sgamma, const float* __restrict__ sbeta,
    float* __restrict__ outp, float* __restrict__ outw)
{
    extern __shared__ float sm[];
    uint32_t* A_hi = (uint32_t*)sm;            // [64][36]
    uint32_t* A_lo = (uint32_t*)(sm + 2304);
    uint32_t* B_hi = (uint32_t*)(sm + 4608);   // [144][36]
    uint32_t* B_lo = (uint32_t*)(sm + 9792);   // ends 14976
    float* sh_hs = sm;            // [64][133] (overlay)
    float* sh_p3 = sm;            // [128][64] (overlay)
    float* sh_o  = sm;            // [64][132] (overlay)
    float* sh_sk = sm + 14976;    // [64][17]
    float* sh_z  = sm + 16064;    // [64][17]
    float* sh_w  = sm + 17152;    // [64][17]
    float* sh_s2 = sm + 18240;    // [16][130]
    float* sh_sg = sm + 20320;    // [16][130] -> total 22400 floats

    const int tid = threadIdx.x, wid = tid >> 5, lane = tid & 31;
    const int mp = wid & 3, nh = wid >> 2;
    const int ar = lane >> 2, ac = lane & 3;
    const int rt = tid & 15, jt = tid >> 4;
    const int tile = blockIdx.x;
    const size_t rowbase = (size_t)tile * 64;
    const float* fbase = g_stackedT + (size_t)tile * 2048 * 64;

    float cfr[9][4];
    #pragma unroll
    for (int nt = 0; nt < 9; nt++)
        #pragma unroll
        for (int q = 0; q < 4; q++) cfr[nt][q] = 0.f;

    const uint32_t sbAh = smaddr(A_hi), sbAl = smaddr(A_lo);
    const uint32_t sbBh = smaddr(B_hi), sbBl = smaddr(B_lo);
    const int lr = lane & 7, lm8 = (lane >> 3) & 1, lt = lane >> 4;
    const uint32_t offA = (uint32_t)((mp * 16 + lr + lm8 * 8) * 36 + lt * 4);
    uint32_t offB[4], offB8;
    #pragma unroll
    for (int p = 0; p < 4; p++)
        offB[p] = (uint32_t)((nh * 72 + p * 16 + lt * 8 + lr) * 36 + lm8 * 4);
    offB8 = (uint32_t)((nh * 72 + 64 + lr) * 36 + lm8 * 4);

    for (int c = 0; c < 32; c++) {
        __syncthreads();
        // A chunk: uint4 plane copies (4/thread)
        for (int idx = tid; idx < 1024; idx += 256) {
            int plane = idx >> 9, j = idx & 511;
            int r = j >> 3, kq = j & 7;
            const uint32_t* src = (plane ? g_Al : g_Ah)
                + (((size_t)tile * 64 + r) << 10) + c * 32 + kq * 4;
            uint32_t* dst = (plane ? A_lo : A_hi) + r * 36 + kq * 4;
            *(uint4*)dst = *(const uint4*)src;
        }
        // B chunk: uint4 plane copies (9/thread)
        for (int idx = tid; idx < 2304; idx += 256) {
            int plane = (idx >= 1152) ? 1 : 0;
            int j = plane ? idx - 1152 : idx;
            int n = j >> 3, kq = j & 7;
            const uint32_t* src = (plane ? g_wBl : g_wBh)
                + ((size_t)n << 10) + c * 32 + kq * 4;
            uint32_t* dst = (plane ? B_lo : B_hi) + n * 36 + kq * 4;
            *(uint4*)dst = *(const uint4*)src;
        }
        __syncthreads();

        #pragma unroll
        for (int ks = 0; ks < 4; ks++) {
            const int k0p = ks * 8;
            uint32_t aH[4], aL[4];
            ldsm4(aH, sbAh + (offA + k0p) * 4);
            ldsm4(aL, sbAl + (offA + k0p) * 4);
            uint32_t bH[18];
            #pragma unroll
            for (int p = 0; p < 4; p++)
                ldsm4(bH + p * 4, sbBh + (offB[p] + k0p) * 4);
            ldsm2(bH + 16, sbBh + (offB8 + k0p) * 4);
            #pragma unroll
            for (int nt = 0; nt < 9; nt++) {
                int base = (nt < 8) ? ((nt >> 1) * 4 + (nt & 1) * 2) : 16;
                uint32_t b0 = bH[base], b1 = bH[base + 1];
                mma16(cfr[nt], aH, b0, b1);
                mma16(cfr[nt], aL, b0, b1);
            }
            uint32_t bL[18];
            #pragma unroll
            for (int p = 0; p < 4; p++)
                ldsm4(bL + p * 4, sbBl + (offB[p] + k0p) * 4);
            ldsm2(bL + 16, sbBl + (offB8 + k0p) * 4);
            #pragma unroll
            for (int nt = 0; nt < 9; nt++) {
                int base = (nt < 8) ? ((nt >> 1) * 4 + (nt & 1) * 2) : 16;
                mma16(cfr[nt], aH, bL[base], bL[base + 1]);
            }
        }
    }
    __syncthreads();

    {
        const int ac2 = ac * 2;
        #pragma unroll
        for (int nt = 0; nt < 9; nt++) {
            #pragma unroll
            for (int q = 0; q < 4; q++) {
                int col = nh * 72 + nt * 8 + ac2 + (q & 1);
                int row = mp * 16 + ar + (q >> 1) * 8;
                float val = cfr[nt][q];
                if (col < 128)
                    sh_hs[row * 133 + col] = eluf(val + sb1[col]);
                else
                    sh_sk[row * 17 + (col - 128)] = val + sbs[col - 128];
            }
        }
    }
    for (int idx = tid; idx < 512; idx += 256) {
        int vv = idx >> 5, jq = (idx & 31) * 4;
        float4 a = *(const float4*)(sW2 + vv * 128 + jq);
        float* p = sh_s2 + vv * 130 + jq;
        p[0] = a.x; p[1] = a.y; p[2] = a.z; p[3] = a.w;
        float4 b = *(const float4*)(sWg + vv * 128 + jq);
        float* q = sh_sg + vv * 130 + jq;
        q[0] = b.x; q[1] = b.y; q[2] = b.z; q[3] = b.w;
    }
    __syncthreads();

    {
        int q = tid & 3, r = tid >> 2;
        float a2[4] = {0.f, 0.f, 0.f, 0.f};
        float ag[4] = {0.f, 0.f, 0.f, 0.f};
        #pragma unroll 4
        for (int j = 0; j < 128; j++) {
            float hsv = sh_hs[r * 133 + j];
            #pragma unroll
            for (int i = 0; i < 4; i++) {
                a2[i] = fmaf(hsv, sh_s2[(q * 4 + i) * 130 + j], a2[i]);
                ag[i] = fmaf(hsv, sh_sg[(q * 4 + i) * 130 + j], ag[i]);
            }
        }
        #pragma unroll
        for (int i = 0; i < 4; i++) {
            int vv = q * 4 + i;
            float h2s = a2[i] + sb2[vv];
            float gs = sigm(ag[i] + sbg[vv]);
            float sk = sh_sk[r * 17 + vv];
            sh_z[r * 17 + vv] = gs * h2s + (1.f - gs) * sk;
        }
    }
    __syncthreads();
    if (tid < 64) {
        float zz[16];
        float s = 0.f;
        #pragma unroll
        for (int vv = 0; vv < 16; vv++) { zz[vv] = sh_z[tid * 17 + vv]; s += zz[vv]; }
        float m = s * 0.0625f;
        float s2 = 0.f;
        #pragma unroll
        for (int vv = 0; vv < 16; vv++) { float d = zz[vv] - m; s2 = fmaf(d, d, s2); }
        float rstd = rsqrtf(s2 * 0.0625f + 1e-5f);
        float mx = -3.4e38f;
        #pragma unroll
        for (int vv = 0; vv < 16; vv++) {
            zz[vv] = fmaf((zz[vv] - m) * rstd, sgamma[vv], sbeta[vv]);
            mx = fmaxf(mx, zz[vv]);
        }
        float se = 0.f;
        #pragma unroll
        for (int vv = 0; vv < 16; vv++) { zz[vv] = __expf(zz[vv] - mx); se += zz[vv]; }
        float inv = __fdividef(1.f, se);
        #pragma unroll
        for (int vv = 0; vv < 16; vv++) sh_w[tid * 17 + vv] = zz[vv] * inv;
    }
    __syncthreads();
    for (int idx = tid; idx < 1024; idx += 256) {
        int r = idx >> 4, vv = idx & 15;
        outw[(rowbase + r) * 16 + vv] = sh_w[r * 17 + vv];
    }

    float accp[32];
    #pragma unroll
    for (int i = 0; i < 32; i++) accp[i] = 0.f;
    for (int vv = 0; vv < 16; vv++) {
        __syncthreads();
        {
            const float4* src = (const float4*)(fbase + (size_t)vv * 128 * 64);
            float4* dst = (float4*)sh_p3;
            for (int idx = tid; idx < 2048; idx += 256) dst[idx] = src[idx];
        }
        __syncthreads();
        float wv0 = sh_w[(rt * 4 + 0) * 17 + vv];
        float wv1 = sh_w[(rt * 4 + 1) * 17 + vv];
        float wv2 = sh_w[(rt * 4 + 2) * 17 + vv];
        float wv3 = sh_w[(rt * 4 + 3) * 17 + vv];
        #pragma unroll
        for (int dd = 0; dd < 8; dd++) {
            float4 fv = *(const float4*)(sh_p3 + (jt * 8 + dd) * 64 + rt * 4);
            accp[0 * 8 + dd] = fmaf(fv.x, wv0, accp[0 * 8 + dd]);
            accp[1 * 8 + dd] = fmaf(fv.y, wv1, accp[1 * 8 + dd]);
            accp[2 * 8 + dd] = fmaf(fv.z, wv2, accp[2 * 8 + dd]);
            accp[3 * 8 + dd] = fmaf(fv.w, wv3, accp[3 * 8 + dd]);
        }
    }
    __syncthreads();
    #pragma unroll
    for (int j = 0; j < 4; j++)
        #pragma unroll
        for (int dd = 0; dd < 8; dd++)
            sh_o[(rt * 4 + j) * 132 + jt * 8 + dd] = accp[j * 8 + dd];
    __syncthreads();
    for (int idx = tid; idx < 2048; idx += 256) {
        int r = idx >> 5, dq = (idx & 31) * 4;
        float4 a = *(const float4*)(sh_o + r * 132 + dq);
        *(float4*)(outp + (rowbase + r) * 128 + dq) = a;
    }
}

extern "C" void kernel_launch(void* const* d_in, const int* in_sizes, int n_in,
                              void* d_out, int out_size) {
    const float* x      = (const float*)d_in[0];
    const float* W1     = (const float*)d_in[1];
    const float* b1     = (const float*)d_in[2];
    const float* W2     = (const float*)d_in[3];
    const float* b2     = (const float*)d_in[4];
    const float* Wg     = (const float*)d_in[5];
    const float* bg     = (const float*)d_in[6];
    const float* Ws     = (const float*)d_in[7];
    const float* bs     = (const float*)d_in[8];
    const float* gamma  = (const float*)d_in[9];
    const float* beta   = (const float*)d_in[10];
    const float* sW1    = (const float*)d_in[11];
    const float* sb1    = (const float*)d_in[12];
    const float* sW2    = (const float*)d_in[13];
    const float* sb2    = (const float*)d_in[14];
    const float* sWg    = (const float*)d_in[15];
    const float* sbg    = (const float*)d_in[16];
    const float* sWs    = (const float*)d_in[17];
    const float* sbs    = (const float*)d_in[18];
    const float* sgamma = (const float*)d_in[19];
    const float* sbeta  = (const float*)d_in[20];

    int N = in_sizes[0] / 16;          // 16384
    int tiles64 = N / 64;              // 256
    int tiles128 = N / 128;            // 128

    float* outp = (float*)d_out;
    float* outw = outp + (size_t)N * 128;

    cudaFuncSetAttribute(vsn_stage1, cudaFuncAttributeMaxDynamicSharedMemorySize,
                         SM1_FLOATS * 4);
    cudaFuncSetAttribute(vsn_stage2, cudaFuncAttributeMaxDynamicSharedMemorySize,
                         S2_FLOATS * 4);

    prep_weights<<<400, 256>>>(sW1, sWs, W2, Wg);
    dim3 g1(tiles128, 16);
    vsn_stage1<<<g1, 512, SM1_FLOATS * 4>>>(x, W1, b1, b2, bg, Ws, bs, gamma, beta);
    vsn_stage2<<<tiles64, 256, S2_FLOATS * 4>>>(sb1, sW2, sb2, sWg, sbg, sbs,
                                                sgamma, sbeta, outp, outw);
}

// round 16
// speedup vs baseline: 1.0909x; 1.0909x over previous
#include <cuda_runtime.h>
#include <cuda_bf16.h>
#include <cstdint>
#include <math.h>

#define NMAX 16384
__device__ __align__(256) float g_stackedT[(size_t)NMAX * 2048];
__device__ __align__(256) uint32_t g_Ah[(size_t)NMAX * 1024];   // [tile][r][kp]
__device__ __align__(256) uint32_t g_Al[(size_t)NMAX * 1024];
__device__ __align__(256) uint32_t g_wBh[144 * 1024];           // [n][kp]
__device__ __align__(256) uint32_t g_wBl[144 * 1024];
__device__ __align__(256) uint32_t g_wSh[16 * 256 * 64];        // [v][n][kp]
__device__ __align__(256) uint32_t g_wSl[16 * 256 * 64];

static __device__ __forceinline__ float eluf(float t) {
    return t > 0.f ? t : __expf(t) - 1.f;
}
static __device__ __forceinline__ float sigm(float t) {
    return __fdividef(1.f, 1.f + __expf(-t));
}
static __device__ __forceinline__ uint32_t pk_bf2(float lo, float hi) {
    uint32_t r;
    asm("cvt.rn.bf16x2.f32 %0, %1, %2;" : "=r"(r) : "f"(hi), "f"(lo));
    return r;
}
static __device__ __forceinline__ void bsplit2(float x0, float x1,
                                               uint32_t& hp, uint32_t& lp) {
    float h0 = __bfloat162float(__float2bfloat16(x0));
    float h1 = __bfloat162float(__float2bfloat16(x1));
    hp = pk_bf2(h0, h1);
    lp = pk_bf2(x0 - h0, x1 - h1);
}
static __device__ __forceinline__ void mma16(float* c, const uint32_t* a,
                                             uint32_t b0, uint32_t b1) {
    asm volatile(
        "mma.sync.aligned.m16n8k16.row.col.f32.bf16.bf16.f32 "
        "{%0,%1,%2,%3}, {%4,%5,%6,%7}, {%8,%9}, {%0,%1,%2,%3};"
        : "+f"(c[0]), "+f"(c[1]), "+f"(c[2]), "+f"(c[3])
        : "r"(a[0]), "r"(a[1]), "r"(a[2]), "r"(a[3]), "r"(b0), "r"(b1));
}
static __device__ __forceinline__ void ldsm4(uint32_t* r, uint32_t a) {
    asm volatile("ldmatrix.sync.aligned.m8n8.x4.shared.b16 {%0,%1,%2,%3}, [%4];"
        : "=r"(r[0]), "=r"(r[1]), "=r"(r[2]), "=r"(r[3]) : "r"(a));
}
static __device__ __forceinline__ void ldsm2(uint32_t* r, uint32_t a) {
    asm volatile("ldmatrix.sync.aligned.m8n8.x2.shared.b16 {%0,%1}, [%2];"
        : "=r"(r[0]), "=r"(r[1]) : "r"(a));
}
static __device__ __forceinline__ uint32_t smaddr(const void* p) {
    return (uint32_t)__cvta_generic_to_shared(p);
}
static __device__ __forceinline__ void cpasync16(uint32_t dst, const void* src) {
    asm volatile("cp.async.ca.shared.global [%0], [%1], 16;" :: "r"(dst), "l"(src));
}
static __device__ __forceinline__ void cp_commit() {
    asm volatile("cp.async.commit_group;" ::: "memory");
}
static __device__ __forceinline__ void cp_wait1() {
    asm volatile("cp.async.wait_group 1;" ::: "memory");
}
static __device__ __forceinline__ void cp_wait0() {
    asm volatile("cp.async.wait_group 0;" ::: "memory");
}

// ---------------------------------------------------------------------------
// prep_weights: one-time bf16 split of all GEMM weights into hi/lo planes.
// ---------------------------------------------------------------------------
__global__ void __launch_bounds__(256) prep_weights(
    const float* __restrict__ sW1, const float* __restrict__ sWs,
    const float* __restrict__ W2, const float* __restrict__ Wg)
{
    const int T1 = 144 * 1024;
    const int T2 = 16 * 256 * 64;
    for (int idx = blockIdx.x * 256 + threadIdx.x; idx < T1 + T2;
         idx += gridDim.x * 256) {
        uint32_t hp, lp;
        if (idx < T1) {
            int n = idx >> 10, kp = idx & 1023;
            const float* src = (n < 128)
                ? sW1 + (size_t)n * 2048 + kp * 2
                : sWs + (size_t)(n - 128) * 2048 + kp * 2;
            float2 a = *(const float2*)src;
            bsplit2(a.x, a.y, hp, lp);
            g_wBh[idx] = hp;
            g_wBl[idx] = lp;
        } else {
            int j = idx - T1;
            int v = j >> 14, rem = j & 16383;
            int n = rem >> 6, kp = rem & 63;
            const float* src = (n < 128)
                ? W2 + ((size_t)v * 128 + n) * 128 + kp * 2
                : Wg + ((size_t)v * 128 + (n - 128)) * 128 + kp * 2;
            float2 a = *(const float2*)src;
            bsplit2(a.x, a.y, hp, lp);
            g_wSh[j] = hp;
            g_wSl[j] = lp;
        }
    }
}

// ---------------------------------------------------------------------------
// Stage 1 (bf16 mma, ldmatrix A+B, plane staging): R15 verbatim.
// grid (N/128, 16), 512 threads.
// ---------------------------------------------------------------------------
#define SM1_FLOATS 36224
__global__ void __launch_bounds__(512, 1) vsn_stage1(
    const float* __restrict__ x,
    const float* __restrict__ W1, const float* __restrict__ b1,
    const float* __restrict__ b2, const float* __restrict__ bg,
    const float* __restrict__ Ws, const float* __restrict__ bs,
    const float* __restrict__ gamma, const float* __restrict__ beta)
{
    extern __shared__ float sm[];
    uint32_t* A_hi = (uint32_t*)sm;            // [128][20]
    uint32_t* A_lo = (uint32_t*)(sm + 2560);
    uint32_t* B_hi = (uint32_t*)(sm + 5120);   // [256][20]
    uint32_t* B_lo = (uint32_t*)(sm + 10240);  // ends 15360
    float* arr1 = sm;               // [128][133] (post-GEMM overlay)
    float* arr2 = sm + 17024;       // [128][133]
    float* par  = sm + 34048;
    float* sx   = sm + 34816;
    float* pmean = sm + 34944;
    float* prstd = sm + 35072;
    float* part_s = sm + 35200;
    float* part_q = sm + 35712;

    const int tid = threadIdx.x, wid = tid >> 5, lane = tid & 31;
    const int mp = wid & 3, nq = wid >> 2;
    const int v = blockIdx.y;
    const int r0 = blockIdx.x * 128;
    const int ar = lane >> 2, ac = lane & 3;

    if (tid < 128) {
        sx[tid] = x[(size_t)(r0 + tid) * 16 + v];
        int o = tid;
        par[o]       = b2[v * 128 + o];
        par[128 + o] = bg[v * 128 + o];
        par[256 + o] = Ws[v * 128 + o];
        par[384 + o] = bs[v * 128 + o];
        par[512 + o] = gamma[v * 128 + o];
        par[640 + o] = beta[v * 128 + o];
    }

    float cfr[2][8][4];
    #pragma unroll
    for (int mi = 0; mi < 2; mi++)
        #pragma unroll
        for (int nt = 0; nt < 8; nt++)
            #pragma unroll
            for (int q = 0; q < 4; q++) cfr[mi][nt][q] = 0.f;

    const uint32_t sbAh = smaddr(A_hi), sbAl = smaddr(A_lo);
    const uint32_t sbBh = smaddr(B_hi), sbBl = smaddr(B_lo);
    const int lr = lane & 7, lm8 = (lane >> 3) & 1, lt = lane >> 4;
    const uint32_t offA = (uint32_t)((mp * 32 + lr + lm8 * 8) * 20 + lt * 4);
    uint32_t offB[4];
    #pragma unroll
    for (int p = 0; p < 4; p++)
        offB[p] = (uint32_t)((nq * 64 + p * 16 + lt * 8 + lr) * 20 + lm8 * 4);

    for (int kc = 0; kc < 4; kc++) {
        __syncthreads();
        const float* W1v = W1 + v * 128 + kc * 32;
        const float* b1v = b1 + v * 128 + kc * 32;
        for (int idx = tid; idx < 2048; idx += 512) {
            int r = idx & 127, kp = idx >> 7;
            int d = kp * 2;
            float xr = sx[r];
            float h0 = eluf(fmaf(xr, W1v[d], b1v[d]));
            float h1 = eluf(fmaf(xr, W1v[d + 1], b1v[d + 1]));
            uint32_t hp, lp;
            bsplit2(h0, h1, hp, lp);
            A_hi[r * 20 + kp] = hp;
            A_lo[r * 20 + kp] = lp;
        }
        for (int idx = tid; idx < 2048; idx += 512) {
            int plane = idx >> 10, j = idx & 1023;
            int n = j >> 2, kq = j & 3;
            const uint32_t* src = (plane ? g_wSl : g_wSh)
                + (((size_t)v * 256 + n) << 6) + kc * 16 + kq * 4;
            uint32_t* dst = (plane ? B_lo : B_hi) + n * 20 + kq * 4;
            *(uint4*)dst = *(const uint4*)src;
        }
        __syncthreads();

        #pragma unroll
        for (int ks = 0; ks < 2; ks++) {
            const int k0p = ks * 8;
            uint32_t aH[2][4], aL[2][4];
            ldsm4(aH[0], sbAh + (offA + k0p) * 4);
            ldsm4(aH[1], sbAh + (offA + 320 + k0p) * 4);
            ldsm4(aL[0], sbAl + (offA + k0p) * 4);
            ldsm4(aL[1], sbAl + (offA + 320 + k0p) * 4);
            uint32_t bH[16];
            #pragma unroll
            for (int p = 0; p < 4; p++)
                ldsm4(bH + p * 4, sbBh + (offB[p] + k0p) * 4);
            #pragma unroll
            for (int nt = 0; nt < 8; nt++) {
                int base = (nt >> 1) * 4 + (nt & 1) * 2;
                uint32_t b0 = bH[base], b1 = bH[base + 1];
                mma16(cfr[0][nt], aH[0], b0, b1);
                mma16(cfr[1][nt], aH[1], b0, b1);
                mma16(cfr[0][nt], aL[0], b0, b1);
                mma16(cfr[1][nt], aL[1], b0, b1);
            }
            uint32_t bL[16];
            #pragma unroll
            for (int p = 0; p < 4; p++)
                ldsm4(bL + p * 4, sbBl + (offB[p] + k0p) * 4);
            #pragma unroll
            for (int nt = 0; nt < 8; nt++) {
                int base = (nt >> 1) * 4 + (nt & 1) * 2;
                uint32_t b0 = bL[base], b1 = bL[base + 1];
                mma16(cfr[0][nt], aH[0], b0, b1);
                mma16(cfr[1][nt], aH[1], b0, b1);
            }
        }
    }
    __syncthreads();

    {
        const int ac2 = ac * 2;
        #pragma unroll
        for (int mi = 0; mi < 2; mi++) {
            #pragma unroll
            for (int half = 0; half < 2; half++) {
                int r = mp * 32 + mi * 16 + ar + half * 8;
                #pragma unroll
                for (int nt = 0; nt < 8; nt++) {
                    int n = (nq & 1) * 64 + nt * 8 + ac2;
                    float v0 = cfr[mi][nt][half * 2];
                    float v1 = cfr[mi][nt][half * 2 + 1];
                    if (nq < 2) {
                        arr1[r * 133 + n]     = v0 + par[n];
                        arr1[r * 133 + n + 1] = v1 + par[n + 1];
                    } else {
                        arr2[r * 133 + n]     = sigm(v0 + par[128 + n]);
                        arr2[r * 133 + n + 1] = sigm(v1 + par[128 + n + 1]);
                    }
                }
            }
        }
    }
    __syncthreads();

    {
        int r = tid & 127, hf = tid >> 7;
        float xr = sx[r];
        float s = 0.f, s2 = 0.f;
        int o0 = hf * 32;
        for (int o = o0; o < o0 + 32; o++) {
            float h2 = arr1[r * 133 + o];
            float g  = arr2[r * 133 + o];
            float sk = fmaf(xr, par[256 + o], par[384 + o]);
            float yv = g * h2 + (1.f - g) * sk;
            arr1[r * 133 + o] = yv;
            s += yv;
            s2 = fmaf(yv, yv, s2);
        }
        part_s[hf * 128 + r] = s;
        part_q[hf * 128 + r] = s2;
    }
    __syncthreads();
    if (tid < 128) {
        float s  = part_s[tid] + part_s[128 + tid] + part_s[256 + tid] + part_s[384 + tid];
        float s2 = part_q[tid] + part_q[128 + tid] + part_q[256 + tid] + part_q[384 + tid];
        float m = s * 0.0078125f;
        pmean[tid] = m;
        prstd[tid] = rsqrtf(fmaf(-m, m, s2 * 0.0078125f) + 1e-5f);
    }
    __syncthreads();

    for (int idx = tid; idx < 16384; idx += 512) {
        int o = idx >> 7, r = idx & 127;
        float val = fmaf((arr1[r * 133 + o] - pmean[r]) * prstd[r],
                         par[512 + o], par[640 + o]);
        arr1[r * 133 + o] = val;
        size_t tile = (size_t)blockIdx.x * 2 + (r >> 6);
        g_stackedT[(tile * 2048 + v * 128 + o) * 64 + (r & 63)] = val;
    }
    __syncthreads();
    for (int idx = tid; idx < 8192; idx += 512) {
        int kpl = idx & 63, r = idx >> 6;
        float v0 = arr1[r * 133 + kpl * 2];
        float v1 = arr1[r * 133 + kpl * 2 + 1];
        uint32_t hp, lp;
        bsplit2(v0, v1, hp, lp);
        size_t tile = (size_t)blockIdx.x * 2 + (r >> 6);
        size_t base = ((tile * 64 + (r & 63)) << 10) + v * 64 + kpl;
        g_Ah[base] = hp;
        g_Al[base] = lp;
    }
}

// ---------------------------------------------------------------------------
// Stage 2 v6: double-buffered cp.async pipeline, 16-kp chunks (64 chunks).
// grid N/64, 256 thr, 2 CTAs/SM. Staging stride 20.
// Smem (u32, per buffer 8320): A_hi 0 / A_lo 1280 / B_hi 2560 / B_lo 5440.
// ---------------------------------------------------------------------------
#define S2_FLOATS 24064
__global__ void __launch_bounds__(256, 2) vsn_stage2(
    const float* __restrict__ sb1,
    const float* __restrict__ sW2, const float* __restrict__ sb2,
    const float* __restrict__ sWg, const float* __restrict__ sbg,
    const float* __restrict__ sbs,
    const float* __restrict__ sgamma, const float* __restrict__ sbeta,
    float* __restrict__ outp, float* __restrict__ outw)
{
    extern __shared__ float sm[];
    float* sh_hs = sm;            // [64][133] (overlay, post-GEMM)
    float* sh_p3 = sm;            // [128][64] (overlay, pass 3)
    float* sh_o  = sm;            // [64][132] (overlay, output staging)
    float* sh_sk = sm + 16640;    // [64][17]
    float* sh_z  = sm + 17728;    // [64][17]
    float* sh_w  = sm + 18816;    // [64][17]
    float* sh_s2 = sm + 19904;    // [16][130]
    float* sh_sg = sm + 21984;    // [16][130] -> total 24064 floats

    const int tid = threadIdx.x, wid = tid >> 5, lane = tid & 31;
    const int mp = wid & 3, nh = wid >> 2;
    const int ar = lane >> 2, ac = lane & 3;
    const int rt = tid & 15, jt = tid >> 4;
    const int tile = blockIdx.x;
    const size_t rowbase = (size_t)tile * 64;
    const float* fbase = g_stackedT + (size_t)tile * 2048 * 64;

    float cfr[9][4];
    #pragma unroll
    for (int nt = 0; nt < 9; nt++)
        #pragma unroll
        for (int q = 0; q < 4; q++) cfr[nt][q] = 0.f;

    const uint32_t sbS = smaddr(sm);
    const int lr = lane & 7, lm8 = (lane >> 3) & 1, lt = lane >> 4;
    const uint32_t offA = (uint32_t)((mp * 16 + lr + lm8 * 8) * 20 + lt * 4);
    uint32_t offB[4], offB8;
    #pragma unroll
    for (int p = 0; p < 4; p++)
        offB[p] = (uint32_t)((nh * 72 + p * 16 + lt * 8 + lr) * 20 + lm8 * 4);
    offB8 = (uint32_t)((nh * 72 + 64 + lr) * 20 + lm8 * 4);

    // chunk issue: A 512 ops + B 1152 ops of 16B cp.async
    auto issue = [&](int c, int buf) {
        uint32_t base = sbS + buf * 33280;
        #pragma unroll
        for (int it = 0; it < 2; it++) {
            int idx = it * 256 + tid;
            int plane = idx >> 8, j = idx & 255;
            int r = j >> 2, seg = j & 3;
            const uint32_t* src = (plane ? g_Al : g_Ah)
                + (((size_t)tile * 64 + r) << 10) + c * 16 + seg * 4;
            cpasync16(base + (plane ? 5120u : 0u) + (uint32_t)(r * 20 + seg * 4) * 4, src);
        }
        #pragma unroll
        for (int it = 0; it < 5; it++) {
            int idx = it * 256 + tid;
            if (idx < 1152) {
                int plane = (idx >= 576) ? 1 : 0;
                int j = plane ? idx - 576 : idx;
                int n = j >> 2, seg = j & 3;
                const uint32_t* src = (plane ? g_wBl : g_wBh)
                    + ((size_t)n << 10) + c * 16 + seg * 4;
                cpasync16(base + 10240u + (plane ? 11520u : 0u)
                          + (uint32_t)(n * 20 + seg * 4) * 4, src);
            }
        }
        cp_commit();
    };

    issue(0, 0);
    for (int c = 0; c < 64; c++) {
        int buf = c & 1;
        if (c < 63) { issue(c + 1, buf ^ 1); cp_wait1(); }
        else cp_wait0();
        __syncthreads();

        uint32_t bA_hi = sbS + buf * 33280;
        uint32_t bA_lo = bA_hi + 5120;
        uint32_t bB_hi = bA_hi + 10240;
        uint32_t bB_lo = bA_hi + 21760;
        #pragma unroll
        for (int ks = 0; ks < 2; ks++) {
            const int k0p = ks * 8;
            uint32_t aH[4], aL[4];
            ldsm4(aH, bA_hi + (offA + k0p) * 4);
            ldsm4(aL, bA_lo + (offA + k0p) * 4);
            uint32_t bH[18];
            #pragma unroll
            for (int p = 0; p < 4; p++)
                ldsm4(bH + p * 4, bB_hi + (offB[p] + k0p) * 4);
            ldsm2(bH + 16, bB_hi + (offB8 + k0p) * 4);
            #pragma unroll
            for (int nt = 0; nt < 9; nt++) {
                int base = (nt < 8) ? ((nt >> 1) * 4 + (nt & 1) * 2) : 16;
                uint32_t b0 = bH[base], b1 = bH[base + 1];
                mma16(cfr[nt], aH, b0, b1);
                mma16(cfr[nt], aL, b0, b1);
            }
            uint32_t bL[18];
            #pragma unroll
            for (int p = 0; p < 4; p++)
                ldsm4(bL + p * 4, bB_lo + (offB[p] + k0p) * 4);
            ldsm2(bL + 16, bB_lo + (offB8 + k0p) * 4);
            #pragma unroll
            for (int nt = 0; nt < 9; nt++) {
                int base = (nt < 8) ? ((nt >> 1) * 4 + (nt & 1) * 2) : 16;
                mma16(cfr[nt], aH, bL[base], bL[base + 1]);
            }
        }
        __syncthreads();
    }

    {
        const int ac2 = ac * 2;
        #pragma unroll
        for (int nt = 0; nt < 9; nt++) {
            #pragma unroll
            for (int q = 0; q < 4; q++) {
                int col = nh * 72 + nt * 8 + ac2 + (q & 1);
                int row = mp * 16 + ar + (q >> 1) * 8;
                float val = cfr[nt][q];
                if (col < 128)
                    sh_hs[row * 133 + col] = eluf(val + sb1[col]);
                else
                    sh_sk[row * 17 + (col - 128)] = val + sbs[col - 128];
            }
        }
    }
    for (int idx = tid; idx < 512; idx += 256) {
        int vv = idx >> 5, jq = (idx & 31) * 4;
        float4 a = *(const float4*)(sW2 + vv * 128 + jq);
        float* p = sh_s2 + vv * 130 + jq;
        p[0] = a.x; p[1] = a.y; p[2] = a.z; p[3] = a.w;
        float4 b = *(const float4*)(sWg + vv * 128 + jq);
        float* q = sh_sg + vv * 130 + jq;
        q[0] = b.x; q[1] = b.y; q[2] = b.z; q[3] = b.w;
    }
    __syncthreads();

    {
        int q = tid & 3, r = tid >> 2;
        float a2[4] = {0.f, 0.f, 0.f, 0.f};
        float ag[4] = {0.f, 0.f, 0.f, 0.f};
        #pragma unroll 4
        for (int j = 0; j < 128; j++) {
            float hsv = sh_hs[r * 133 + j];
            #pragma unroll
            for (int i = 0; i < 4; i++) {
                a2[i] = fmaf(hsv, sh_s2[(q * 4 + i) * 130 + j], a2[i]);
                ag[i] = fmaf(hsv, sh_sg[(q * 4 + i) * 130 + j], ag[i]);
            }
        }
        #pragma unroll
        for (int i = 0; i < 4; i++) {
            int vv = q * 4 + i;
            float h2s = a2[i] + sb2[vv];
            float gs = sigm(ag[i] + sbg[vv]);
            float sk = sh_sk[r * 17 + vv];
            sh_z[r * 17 + vv] = gs * h2s + (1.f - gs) * sk;
        }
    }
    __syncthreads();
    if (tid < 64) {
        float zz[16];
        float s = 0.f;
        #pragma unroll
        for (int vv = 0; vv < 16; vv++) { zz[vv] = sh_z[tid * 17 + vv]; s += zz[vv]; }
        float m = s * 0.0625f;
        float s2 = 0.f;
        #pragma unroll
        for (int vv = 0; vv < 16; vv++) { float d = zz[vv] - m; s2 = fmaf(d, d, s2); }
        float rstd = rsqrtf(s2 * 0.0625f + 1e-5f);
        float mx = -3.4e38f;
        #pragma unroll
        for (int vv = 0; vv < 16; vv++) {
            zz[vv] = fmaf((zz[vv] - m) * rstd, sgamma[vv], sbeta[vv]);
            mx = fmaxf(mx, zz[vv]);
        }
        float se = 0.f;
        #pragma unroll
        for (int vv = 0; vv < 16; vv++) { zz[vv] = __expf(zz[vv] - mx); se += zz[vv]; }
        float inv = __fdividef(1.f, se);
        #pragma unroll
        for (int vv = 0; vv < 16; vv++) sh_w[tid * 17 + vv] = zz[vv] * inv;
    }
    __syncthreads();
    for (int idx = tid; idx < 1024; idx += 256) {
        int r = idx >> 4, vv = idx & 15;
        outw[(rowbase + r) * 16 + vv] = sh_w[r * 17 + vv];
    }

    float accp[32];
    #pragma unroll
    for (int i = 0; i < 32; i++) accp[i] = 0.f;
    for (int vv = 0; vv < 16; vv++) {
        __syncthreads();
        {
            const float4* src = (const float4*)(fbase + (size_t)vv * 128 * 64);
            float4* dst = (float4*)sh_p3;
            for (int idx = tid; idx < 2048; idx += 256) dst[idx] = src[idx];
        }
        __syncthreads();
        float wv0 = sh_w[(rt * 4 + 0) * 17 + vv];
        float wv1 = sh_w[(rt * 4 + 1) * 17 + vv];
        float wv2 = sh_w[(rt * 4 + 2) * 17 + vv];
        float wv3 = sh_w[(rt * 4 + 3) * 17 + vv];
        #pragma unroll
        for (int dd = 0; dd < 8; dd++) {
            float4 fv = *(const float4*)(sh_p3 + (jt * 8 + dd) * 64 + rt * 4);
            accp[0 * 8 + dd] = fmaf(fv.x, wv0, accp[0 * 8 + dd]);
            accp[1 * 8 + dd] = fmaf(fv.y, wv1, accp[1 * 8 + dd]);
            accp[2 * 8 + dd] = fmaf(fv.z, wv2, accp[2 * 8 + dd]);
            accp[3 * 8 + dd] = fmaf(fv.w, wv3, accp[3 * 8 + dd]);
        }
    }
    __syncthreads();
    #pragma unroll
    for (int j = 0; j < 4; j++)
        #pragma unroll
        for (int dd = 0; dd < 8; dd++)
            sh_o[(rt * 4 + j) * 132 + jt * 8 + dd] = accp[j * 8 + dd];
    __syncthreads();
    for (int idx = tid; idx < 2048; idx += 256) {
        int r = idx >> 5, dq = (idx & 31) * 4;
        float4 a = *(const float4*)(sh_o + r * 132 + dq);
        *(float4*)(outp + (rowbase + r) * 128 + dq) = a;
    }
}

extern "C" void kernel_launch(void* const* d_in, const int* in_sizes, int n_in,
                              void* d_out, int out_size) {
    const float* x      = (const float*)d_in[0];
    const float* W1     = (const float*)d_in[1];
    const float* b1     = (const float*)d_in[2];
    const float* W2     = (const float*)d_in[3];
    const float* b2     = (const float*)d_in[4];
    const float* Wg     = (const float*)d_in[5];
    const float* bg     = (const float*)d_in[6];
    const float* Ws     = (const float*)d_in[7];
    const float* bs     = (const float*)d_in[8];
    const float* gamma  = (const float*)d_in[9];
    const float* beta   = (const float*)d_in[10];
    const float* sW1    = (const float*)d_in[11];
    const float* sb1    = (const float*)d_in[12];
    const float* sW2    = (const float*)d_in[13];
    const float* sb2    = (const float*)d_in[14];
    const float* sWg    = (const float*)d_in[15];
    const float* sbg    = (const float*)d_in[16];
    const float* sWs    = (const float*)d_in[17];
    const float* sbs    = (const float*)d_in[18];
    const float* sgamma = (const float*)d_in[19];
    const float* sbeta  = (const float*)d_in[20];

    int N = in_sizes[0] / 16;          // 16384
    int tiles64 = N / 64;              // 256
    int tiles128 = N / 128;            // 128

    float* outp = (float*)d_out;
    float* outw = outp + (size_t)N * 128;

    cudaFuncSetAttribute(vsn_stage1, cudaFuncAttributeMaxDynamicSharedMemorySize,
                         SM1_FLOATS * 4);
    cudaFuncSetAttribute(vsn_stage2, cudaFuncAttributeMaxDynamicSharedMemorySize,
                         S2_FLOATS * 4);

    prep_weights<<<400, 256>>>(sW1, sWs, W2, Wg);
    dim3 g1(tiles128, 16);
    vsn_stage1<<<g1, 512, SM1_FLOATS * 4>>>(x, W1, b1, b2, bg, Ws, bs, gamma, beta);
    vsn_stage2<<<tiles64, 256, S2_FLOATS * 4>>>(sb1, sW2, sb2, sWg, sbg, sbs,
                                                sgamma, sbeta, outp, outw);
}